// round 5
// baseline (speedup 1.0000x reference)
#include <cuda_runtime.h>
#include <float.h>

#define N_REF   500000
#define N_PC    128
#define N_FEAT  2000
#define TOP_K   16

#define BLOCKS           296
#define THREADS          256
#define WARPS_PER_BLOCK  (THREADS / 32)
#define TOTAL_WARPS      (BLOCKS * WARPS_PER_BLOCK)   // 2368
#define N_CAND           (BLOCKS * TOP_K)             // 4736
#define M1_BLOCKS        19                           // 19*256 = 4864 >= 4736
#define N_CAND2          (M1_BLOCKS * TOP_K)          // 304

#define PROJ_BLOCKS      50
#define FEAT_PER_BLOCK   (N_FEAT / PROJ_BLOCKS)       // 40

// Scratch (no cudaMalloc allowed)
__device__ float g_qpart[PROJ_BLOCKS * N_PC];
__device__ float g_query[N_PC];
__device__ float g_cand_d[N_CAND];
__device__ int   g_cand_i[N_CAND];
__device__ float g_cand2_d[N_CAND2];
__device__ int   g_cand2_i[N_CAND2];

// ---------------------------------------------------------------------------
// Branch-free register top-16 insert (only at lane 0 of streaming warps,
// where it's rare and hidden behind DRAM latency).
// ---------------------------------------------------------------------------
__device__ __forceinline__ void bubble_insert(float (&d)[TOP_K], int (&ix)[TOP_K],
                                              float v, int id) {
    #pragma unroll
    for (int t = 0; t < TOP_K; t++) {
        bool sw  = v < d[t];
        float tv = d[t];
        int   ti = ix[t];
        d[t]  = sw ? v  : tv;
        ix[t] = sw ? id : ti;
        v     = sw ? tv : v;
        id    = sw ? ti : id;
    }
}

// ---------------------------------------------------------------------------
// Full bitonic sort of 32 (v,i) pairs across a warp (ascending by lane).
// ---------------------------------------------------------------------------
__device__ __forceinline__ void bitonic32(float& v, int& i, int lane) {
    #pragma unroll
    for (int k = 2; k <= 32; k <<= 1) {
        #pragma unroll
        for (int j = k >> 1; j > 0; j >>= 1) {
            float ov = __shfl_xor_sync(0xFFFFFFFFu, v, j);
            int   oi = __shfl_xor_sync(0xFFFFFFFFu, i, j);
            bool up      = ((lane & k) == 0);
            bool lower   = ((lane & j) == 0);
            bool takeMin = (lower == up);
            bool sel = takeMin ? (ov < v) : (ov > v);
            v = sel ? ov : v;
            i = sel ? oi : i;
        }
    }
}

// ---------------------------------------------------------------------------
// Kernel A1/A2: query projection
// ---------------------------------------------------------------------------
__global__ void project_partial(const float* __restrict__ data_in,
                                const float* __restrict__ tmat) {
    int j  = threadIdx.x;
    int b  = blockIdx.x;
    int k0 = b * FEAT_PER_BLOCK;
    float acc = 0.0f;
    #pragma unroll 8
    for (int k = k0; k < k0 + FEAT_PER_BLOCK; k++)
        acc += data_in[k] * tmat[k * N_PC + j];
    g_qpart[b * N_PC + j] = acc;
}

__global__ void project_reduce() {
    int j = threadIdx.x;
    float acc = 0.0f;
    #pragma unroll
    for (int b = 0; b < PROJ_BLOCKS; b++) acc += g_qpart[b * N_PC + j];
    g_query[j] = acc;
}

// ---------------------------------------------------------------------------
// Kernel B: streaming L1 distance + per-warp top-16 + parallel rank-select
// block top-16. One warp per row; lane l reads one float4 (512B/row,
// coalesced). 8-row unroll -> MLP=8/lane.
// ---------------------------------------------------------------------------
__global__ void __launch_bounds__(THREADS)
dist_topk_kernel(const float* __restrict__ ref) {
    const int lane = threadIdx.x & 31;
    const int wid  = threadIdx.x >> 5;
    const int gw   = blockIdx.x * WARPS_PER_BLOCK + wid;

    const float4 q = reinterpret_cast<const float4*>(g_query)[lane];

    const int chunk = (N_REF + TOTAL_WARPS - 1) / TOTAL_WARPS;  // 212
    int start = gw * chunk;
    int end   = start + chunk;
    if (start > N_REF) start = N_REF;
    if (end   > N_REF) end   = N_REF;

    float topd[TOP_K];
    int   topi[TOP_K];
    #pragma unroll
    for (int t = 0; t < TOP_K; t++) { topd[t] = FLT_MAX; topi[t] = 0; }
    float kmax = FLT_MAX;

    const float4* __restrict__ ref4 = reinterpret_cast<const float4*>(ref);

    int r = start;
    for (; r + 8 <= end; r += 8) {
        float4 a[8];
        #pragma unroll
        for (int u = 0; u < 8; u++)
            a[u] = __ldcs(ref4 + (size_t)(r + u) * (N_PC / 4) + lane);

        float s[8];
        #pragma unroll
        for (int u = 0; u < 8; u++)
            s[u] = fabsf(a[u].x - q.x) + fabsf(a[u].y - q.y)
                 + fabsf(a[u].z - q.z) + fabsf(a[u].w - q.w);

        #pragma unroll
        for (int off = 16; off > 0; off >>= 1) {
            #pragma unroll
            for (int u = 0; u < 8; u++)
                s[u] += __shfl_xor_sync(0xFFFFFFFFu, s[u], off);
        }

        if (lane == 0) {
            #pragma unroll
            for (int u = 0; u < 8; u++) {
                if (s[u] < kmax) {
                    bubble_insert(topd, topi, s[u], r + u);
                    kmax = topd[TOP_K - 1];
                }
            }
        }
    }
    for (; r < end; r++) {
        float4 a0 = __ldcs(ref4 + (size_t)r * (N_PC / 4) + lane);
        float s0 = fabsf(a0.x - q.x) + fabsf(a0.y - q.y)
                 + fabsf(a0.z - q.z) + fabsf(a0.w - q.w);
        #pragma unroll
        for (int off = 16; off > 0; off >>= 1)
            s0 += __shfl_xor_sync(0xFFFFFFFFu, s0, off);
        if (lane == 0 && s0 < kmax) {
            bubble_insert(topd, topi, s0, r);
            kmax = topd[TOP_K - 1];
        }
    }

    // ---- parallel rank-select block top-16 over 128 shared entries ----
    __shared__ float sbd[WARPS_PER_BLOCK * TOP_K];   // 128
    __shared__ int   sbi[WARPS_PER_BLOCK * TOP_K];
    if (lane == 0) {
        #pragma unroll
        for (int t = 0; t < TOP_K; t++) {
            sbd[wid * TOP_K + t] = topd[t];
            sbi[wid * TOP_K + t] = topi[t];
        }
    }
    __syncthreads();

    const int tid = threadIdx.x;
    if (tid < 128) {
        float v  = sbd[tid];
        int   id = sbi[tid];
        int rank = 0;
        #pragma unroll 8
        for (int j = 0; j < 128; j++) {
            float o = sbd[j];
            rank += (o < v) || (o == v && j < tid);
        }
        if (rank < TOP_K) {
            g_cand_d[blockIdx.x * TOP_K + rank] = v;
            g_cand_i[blockIdx.x * TOP_K + rank] = id;
        }
    }
}

// ---------------------------------------------------------------------------
// Kernel C1: 19 blocks x 256 threads; 1 candidate/thread.
// warp bitonic sort-32 -> top-16/warp -> 128 shared -> rank-select top-16.
// 4736 -> 304 candidates.
// ---------------------------------------------------------------------------
__global__ void merge1_kernel() {
    const int tid  = threadIdx.x;
    const int lane = tid & 31;
    const int wid  = tid >> 5;

    int c = blockIdx.x * 256 + tid;
    bool ok = (c < N_CAND);
    float v  = ok ? g_cand_d[c] : FLT_MAX;
    int   id = ok ? g_cand_i[c] : 0;

    bitonic32(v, id, lane);

    __shared__ float sd[WARPS_PER_BLOCK * TOP_K];   // 128
    __shared__ int   si[WARPS_PER_BLOCK * TOP_K];
    if (lane < TOP_K) {
        sd[wid * TOP_K + lane] = v;
        si[wid * TOP_K + lane] = id;
    }
    __syncthreads();

    if (tid < 128) {
        float vv = sd[tid];
        int   ii = si[tid];
        int rank = 0;
        #pragma unroll 8
        for (int j = 0; j < 128; j++) {
            float o = sd[j];
            rank += (o < vv) || (o == vv && j < tid);
        }
        if (rank < TOP_K) {
            g_cand2_d[blockIdx.x * TOP_K + rank] = vv;
            g_cand2_i[blockIdx.x * TOP_K + rank] = ii;
        }
    }
}

// ---------------------------------------------------------------------------
// Kernel C2: 1 block x 320 threads; rank-select top-16 of 304, then
// deterministic gather + mean.
// ---------------------------------------------------------------------------
__global__ void merge2_kernel(const float* __restrict__ psuedo,
                              float* __restrict__ out) {
    const int tid = threadIdx.x;

    __shared__ float sd[N_CAND2];
    __shared__ int   si[N_CAND2];
    __shared__ float s_sel[TOP_K];

    if (tid < N_CAND2) {
        sd[tid] = g_cand2_d[tid];
        si[tid] = g_cand2_i[tid];
    }
    __syncthreads();

    if (tid < N_CAND2) {
        float v = sd[tid];
        int rank = 0;
        #pragma unroll 8
        for (int j = 0; j < N_CAND2; j++) {
            float o = sd[j];
            rank += (o < v) || (o == v && j < tid);
        }
        if (rank < TOP_K) s_sel[rank] = psuedo[si[tid]];
    }
    __syncthreads();

    if (tid < 32) {
        float v = (tid < TOP_K) ? s_sel[tid] : 0.0f;
        #pragma unroll
        for (int off = 16; off > 0; off >>= 1)
            v += __shfl_xor_sync(0xFFFFFFFFu, v, off);
        if (tid == 0) out[0] = v * (1.0f / TOP_K);
    }
}

// ---------------------------------------------------------------------------
// Launch
// ---------------------------------------------------------------------------
extern "C" void kernel_launch(void* const* d_in, const int* in_sizes, int n_in,
                              void* d_out, int out_size) {
    const float* data_in = (const float*)d_in[0];
    const float* tmat    = (const float*)d_in[1];
    const float* ref     = (const float*)d_in[2];
    const float* psuedo  = (const float*)d_in[3];
    float* out = (float*)d_out;

    project_partial<<<PROJ_BLOCKS, N_PC>>>(data_in, tmat);
    project_reduce<<<1, N_PC>>>();
    dist_topk_kernel<<<BLOCKS, THREADS>>>(ref);
    merge1_kernel<<<M1_BLOCKS, 256>>>();
    merge2_kernel<<<1, 320>>>(psuedo, out);
}

// round 6
// speedup vs baseline: 1.1474x; 1.1474x over previous
#include <cuda_runtime.h>
#include <float.h>

#define N_REF   500000
#define N_PC    128
#define N_FEAT  2000
#define TOP_K   16

#define BLOCKS           592
#define THREADS          256
#define WARPS_PER_BLOCK  (THREADS / 32)
#define TOTAL_WARPS      (BLOCKS * WARPS_PER_BLOCK)   // 4736
#define N_CAND           (BLOCKS * TOP_K)             // 9472
#define M1_BLOCKS        37                           // 37*256 = 9472 exactly
#define N_CAND2          (M1_BLOCKS * TOP_K)          // 592

#define PROJ_BLOCKS      50
#define FEAT_PER_BLOCK   (N_FEAT / PROJ_BLOCKS)       // 40

// Scratch (no cudaMalloc allowed)
__device__ float g_qpart[PROJ_BLOCKS * N_PC];
__device__ float g_query[N_PC];
__device__ float g_cand_d[N_CAND];
__device__ int   g_cand_i[N_CAND];
__device__ float g_cand2_d[N_CAND2];
__device__ int   g_cand2_i[N_CAND2];
__device__ int   g_merge_tix;   // zero-initialized; reset by last block each run

// ---------------------------------------------------------------------------
// Branch-free register top-16 insert (lane 0 of streaming warps only; rare
// and hidden behind DRAM latency).
// ---------------------------------------------------------------------------
__device__ __forceinline__ void bubble_insert(float (&d)[TOP_K], int (&ix)[TOP_K],
                                              float v, int id) {
    #pragma unroll
    for (int t = 0; t < TOP_K; t++) {
        bool sw  = v < d[t];
        float tv = d[t];
        int   ti = ix[t];
        d[t]  = sw ? v  : tv;
        ix[t] = sw ? id : ti;
        v     = sw ? tv : v;
        id    = sw ? ti : id;
    }
}

// ---------------------------------------------------------------------------
// Full bitonic sort of 32 (v,i) pairs across a warp (ascending by lane).
// ---------------------------------------------------------------------------
__device__ __forceinline__ void bitonic32(float& v, int& i, int lane) {
    #pragma unroll
    for (int k = 2; k <= 32; k <<= 1) {
        #pragma unroll
        for (int j = k >> 1; j > 0; j >>= 1) {
            float ov = __shfl_xor_sync(0xFFFFFFFFu, v, j);
            int   oi = __shfl_xor_sync(0xFFFFFFFFu, i, j);
            bool up      = ((lane & k) == 0);
            bool lower   = ((lane & j) == 0);
            bool takeMin = (lower == up);
            bool sel = takeMin ? (ov < v) : (ov > v);
            v = sel ? ov : v;
            i = sel ? oi : i;
        }
    }
}

// ---------------------------------------------------------------------------
// Kernel A1/A2: query projection
// ---------------------------------------------------------------------------
__global__ void project_partial(const float* __restrict__ data_in,
                                const float* __restrict__ tmat) {
    int j  = threadIdx.x;
    int b  = blockIdx.x;
    int k0 = b * FEAT_PER_BLOCK;
    float acc = 0.0f;
    #pragma unroll 8
    for (int k = k0; k < k0 + FEAT_PER_BLOCK; k++)
        acc += data_in[k] * tmat[k * N_PC + j];
    g_qpart[b * N_PC + j] = acc;
}

__global__ void project_reduce() {
    int j = threadIdx.x;
    float acc = 0.0f;
    #pragma unroll
    for (int b = 0; b < PROJ_BLOCKS; b++) acc += g_qpart[b * N_PC + j];
    g_query[j] = acc;
}

// ---------------------------------------------------------------------------
// Kernel B: streaming L1 distance (R4 config: 592 blocks, 4-row unroll,
// MLP=4/lane) + per-warp top-16 + parallel rank-select block top-16 tail.
// ---------------------------------------------------------------------------
__global__ void __launch_bounds__(THREADS)
dist_topk_kernel(const float* __restrict__ ref) {
    const int lane = threadIdx.x & 31;
    const int wid  = threadIdx.x >> 5;
    const int gw   = blockIdx.x * WARPS_PER_BLOCK + wid;

    const float4 q = reinterpret_cast<const float4*>(g_query)[lane];

    const int chunk = (N_REF + TOTAL_WARPS - 1) / TOTAL_WARPS;  // 106
    int start = gw * chunk;
    int end   = start + chunk;
    if (start > N_REF) start = N_REF;
    if (end   > N_REF) end   = N_REF;

    float topd[TOP_K];
    int   topi[TOP_K];
    #pragma unroll
    for (int t = 0; t < TOP_K; t++) { topd[t] = FLT_MAX; topi[t] = 0; }
    float kmax = FLT_MAX;

    const float4* __restrict__ ref4 = reinterpret_cast<const float4*>(ref);

    int r = start;
    for (; r + 4 <= end; r += 4) {
        float4 a0 = __ldcs(ref4 + (size_t)(r + 0) * (N_PC / 4) + lane);
        float4 a1 = __ldcs(ref4 + (size_t)(r + 1) * (N_PC / 4) + lane);
        float4 a2 = __ldcs(ref4 + (size_t)(r + 2) * (N_PC / 4) + lane);
        float4 a3 = __ldcs(ref4 + (size_t)(r + 3) * (N_PC / 4) + lane);

        float s0 = fabsf(a0.x - q.x) + fabsf(a0.y - q.y) + fabsf(a0.z - q.z) + fabsf(a0.w - q.w);
        float s1 = fabsf(a1.x - q.x) + fabsf(a1.y - q.y) + fabsf(a1.z - q.z) + fabsf(a1.w - q.w);
        float s2 = fabsf(a2.x - q.x) + fabsf(a2.y - q.y) + fabsf(a2.z - q.z) + fabsf(a2.w - q.w);
        float s3 = fabsf(a3.x - q.x) + fabsf(a3.y - q.y) + fabsf(a3.z - q.z) + fabsf(a3.w - q.w);

        #pragma unroll
        for (int off = 16; off > 0; off >>= 1) {
            s0 += __shfl_xor_sync(0xFFFFFFFFu, s0, off);
            s1 += __shfl_xor_sync(0xFFFFFFFFu, s1, off);
            s2 += __shfl_xor_sync(0xFFFFFFFFu, s2, off);
            s3 += __shfl_xor_sync(0xFFFFFFFFu, s3, off);
        }

        if (lane == 0) {
            if (s0 < kmax) { bubble_insert(topd, topi, s0, r + 0); kmax = topd[TOP_K - 1]; }
            if (s1 < kmax) { bubble_insert(topd, topi, s1, r + 1); kmax = topd[TOP_K - 1]; }
            if (s2 < kmax) { bubble_insert(topd, topi, s2, r + 2); kmax = topd[TOP_K - 1]; }
            if (s3 < kmax) { bubble_insert(topd, topi, s3, r + 3); kmax = topd[TOP_K - 1]; }
        }
    }
    for (; r < end; r++) {
        float4 a0 = __ldcs(ref4 + (size_t)r * (N_PC / 4) + lane);
        float s0 = fabsf(a0.x - q.x) + fabsf(a0.y - q.y) + fabsf(a0.z - q.z) + fabsf(a0.w - q.w);
        #pragma unroll
        for (int off = 16; off > 0; off >>= 1)
            s0 += __shfl_xor_sync(0xFFFFFFFFu, s0, off);
        if (lane == 0 && s0 < kmax) {
            bubble_insert(topd, topi, s0, r);
            kmax = topd[TOP_K - 1];
        }
    }

    // ---- parallel rank-select block top-16 over 128 shared entries ----
    __shared__ float sbd[WARPS_PER_BLOCK * TOP_K];   // 128
    __shared__ int   sbi[WARPS_PER_BLOCK * TOP_K];
    if (lane == 0) {
        #pragma unroll
        for (int t = 0; t < TOP_K; t++) {
            sbd[wid * TOP_K + t] = topd[t];
            sbi[wid * TOP_K + t] = topi[t];
        }
    }
    __syncthreads();

    const int tid = threadIdx.x;
    if (tid < 128) {
        float v  = sbd[tid];
        int   id = sbi[tid];
        int rank = 0;
        #pragma unroll 8
        for (int j = 0; j < 128; j++) {
            float o = sbd[j];
            rank += (o < v) || (o == v && j < tid);
        }
        if (rank < TOP_K) {
            g_cand_d[blockIdx.x * TOP_K + rank] = v;
            g_cand_i[blockIdx.x * TOP_K + rank] = id;
        }
    }
}

// ---------------------------------------------------------------------------
// Kernel C (fused): 37 blocks x 256 threads.
// Stage 1 (all blocks): 1 candidate/thread, warp bitonic sort-32 ->
//   top-16/warp -> 128 shared -> rank-select block top-16 -> g_cand2.
// Stage 2 (last block to finish, via atomic ticket): rank-select top-16 of
//   592 survivors, gather psuedo, write mean. Resets ticket for graph replay.
// ---------------------------------------------------------------------------
__global__ void merge_kernel(const float* __restrict__ psuedo,
                             float* __restrict__ out) {
    const int tid  = threadIdx.x;
    const int lane = tid & 31;
    const int wid  = tid >> 5;

    // ---- Stage 1 ----
    {
        int c = blockIdx.x * 256 + tid;           // 37*256 == N_CAND exactly
        float v  = g_cand_d[c];
        int   id = g_cand_i[c];

        bitonic32(v, id, lane);

        __shared__ float sd[WARPS_PER_BLOCK * TOP_K];   // 128
        __shared__ int   si[WARPS_PER_BLOCK * TOP_K];
        if (lane < TOP_K) {
            sd[wid * TOP_K + lane] = v;
            si[wid * TOP_K + lane] = id;
        }
        __syncthreads();

        if (tid < 128) {
            float vv = sd[tid];
            int   ii = si[tid];
            int rank = 0;
            #pragma unroll 8
            for (int j = 0; j < 128; j++) {
                float o = sd[j];
                rank += (o < vv) || (o == vv && j < tid);
            }
            if (rank < TOP_K) {
                g_cand2_d[blockIdx.x * TOP_K + rank] = vv;
                g_cand2_i[blockIdx.x * TOP_K + rank] = ii;
            }
        }
    }

    // ---- ticket: last block does the final reduction ----
    __threadfence();
    __syncthreads();
    __shared__ int s_last;
    if (tid == 0) {
        int t = atomicAdd(&g_merge_tix, 1);
        s_last = (t == M1_BLOCKS - 1);
    }
    __syncthreads();
    if (!s_last) return;

    if (tid == 0) g_merge_tix = 0;   // reset for next graph replay
    __threadfence();

    // ---- Stage 2: rank-select top-16 of 592 + gather + mean ----
    __shared__ float fd[N_CAND2];
    __shared__ int   fi[N_CAND2];
    __shared__ float s_sel[TOP_K];

    #pragma unroll
    for (int t = 0; t < 3; t++) {
        int c = tid + t * 256;
        if (c < N_CAND2) {
            fd[c] = g_cand2_d[c];
            fi[c] = g_cand2_i[c];
        }
    }
    __syncthreads();

    #pragma unroll
    for (int t = 0; t < 3; t++) {
        int c = tid + t * 256;
        if (c < N_CAND2) {
            float v = fd[c];
            int rank = 0;
            #pragma unroll 8
            for (int j = 0; j < N_CAND2; j++) {
                float o = fd[j];
                rank += (o < v) || (o == v && j < c);
            }
            if (rank < TOP_K) s_sel[rank] = psuedo[fi[c]];
        }
    }
    __syncthreads();

    if (tid < 32) {
        float v = (tid < TOP_K) ? s_sel[tid] : 0.0f;
        #pragma unroll
        for (int off = 16; off > 0; off >>= 1)
            v += __shfl_xor_sync(0xFFFFFFFFu, v, off);
        if (tid == 0) out[0] = v * (1.0f / TOP_K);
    }
}

// ---------------------------------------------------------------------------
// Launch (4 kernels)
// ---------------------------------------------------------------------------
extern "C" void kernel_launch(void* const* d_in, const int* in_sizes, int n_in,
                              void* d_out, int out_size) {
    const float* data_in = (const float*)d_in[0];
    const float* tmat    = (const float*)d_in[1];
    const float* ref     = (const float*)d_in[2];
    const float* psuedo  = (const float*)d_in[3];
    float* out = (float*)d_out;

    project_partial<<<PROJ_BLOCKS, N_PC>>>(data_in, tmat);
    project_reduce<<<1, N_PC>>>();
    dist_topk_kernel<<<BLOCKS, THREADS>>>(ref);
    merge_kernel<<<M1_BLOCKS, 256>>>(psuedo, out);
}